// round 5
// baseline (speedup 1.0000x reference)
#include <cuda_runtime.h>
#include <cuda_bf16.h>
#include <cstdint>

// CenterLoss: mean_b clip(||x_b - centers[labels[b]]||^2, 1e-12, 1e12)
// x: [B, D] f32, labels: [B] int32 (harness downcasts int64), centers: [C, D] f32.
// out: scalar f32. Pure HBM-streaming (~34 MB); skip the reference's BxC GEMM.

#define CLAMP_MIN 1e-12f
#define CLAMP_MAX 1e12f

#define WARPS_PER_BLOCK 8
#define MAX_BLOCKS 8192   // supports B up to 65536 at 8 warps/block

__device__ float g_partials[MAX_BLOCKS];

__global__ __launch_bounds__(WARPS_PER_BLOCK * 32)
void center_dist_kernel(const float* __restrict__ x,
                        const int* __restrict__ labels,
                        const float* __restrict__ centers,
                        int B, int D, int C)
{
    const int lane = threadIdx.x & 31;
    const int warp = threadIdx.x >> 5;
    const int b    = blockIdx.x * WARPS_PER_BLOCK + warp;

    float dist = 0.0f;
    if (b < B) {
        int lbl = labels[b];
        // Defensive clamp: never generate an OOB gather even if dtype/layout
        // assumptions are off (wrong value would then show as rel_err, not a crash).
        lbl = min(max(lbl, 0), C - 1);

        const float4* __restrict__ xr = (const float4*)(x + (size_t)b * D);
        const float4* __restrict__ cr = (const float4*)(centers + (size_t)lbl * D);
        const int nvec = D >> 2;  // D=512 -> 128 float4s, 4 iters/lane

        float acc0 = 0.0f, acc1 = 0.0f, acc2 = 0.0f, acc3 = 0.0f;
        #pragma unroll 4
        for (int i = lane; i < nvec; i += 32) {
            float4 xv = __ldg(&xr[i]);
            float4 cv = __ldg(&cr[i]);
            float d0 = xv.x - cv.x;
            float d1 = xv.y - cv.y;
            float d2 = xv.z - cv.z;
            float d3 = xv.w - cv.w;
            acc0 = fmaf(d0, d0, acc0);
            acc1 = fmaf(d1, d1, acc1);
            acc2 = fmaf(d2, d2, acc2);
            acc3 = fmaf(d3, d3, acc3);
        }
        dist = (acc0 + acc1) + (acc2 + acc3);
    }

    // Warp reduce
    #pragma unroll
    for (int off = 16; off > 0; off >>= 1)
        dist += __shfl_xor_sync(0xFFFFFFFFu, dist, off);

    __shared__ float s_warp[WARPS_PER_BLOCK];
    if (lane == 0) {
        // per-sample clip BEFORE summing (matches reference semantics)
        float d = fminf(fmaxf(dist, CLAMP_MIN), CLAMP_MAX);
        if (b >= B) d = 0.0f;
        s_warp[warp] = d;
    }
    __syncthreads();

    if (warp == 0) {
        float v = (lane < WARPS_PER_BLOCK) ? s_warp[lane] : 0.0f;
        #pragma unroll
        for (int off = 16; off > 0; off >>= 1)
            v += __shfl_xor_sync(0xFFFFFFFFu, v, off);
        if (lane == 0)
            g_partials[blockIdx.x] = v;
    }
}

__global__ __launch_bounds__(1024)
void finalize_kernel(float* __restrict__ out, int nblocks, float inv_B)
{
    const int tid = threadIdx.x;
    float v = 0.0f;
    for (int i = tid; i < nblocks; i += 1024)
        v += g_partials[i];

    #pragma unroll
    for (int off = 16; off > 0; off >>= 1)
        v += __shfl_xor_sync(0xFFFFFFFFu, v, off);

    __shared__ float s[32];
    if ((tid & 31) == 0) s[tid >> 5] = v;
    __syncthreads();
    if (tid < 32) {
        float w = (tid < (1024 / 32)) ? s[tid] : 0.0f;
        #pragma unroll
        for (int off = 16; off > 0; off >>= 1)
            w += __shfl_xor_sync(0xFFFFFFFFu, w, off);
        if (tid == 0)
            out[0] = w * inv_B;
    }
}

extern "C" void kernel_launch(void* const* d_in, const int* in_sizes, int n_in,
                              void* d_out, int out_size)
{
    const float* x       = (const float*)d_in[0];
    const int*   labels  = (const int*)d_in[1];
    const float* centers = (const float*)d_in[2];
    float*       out     = (float*)d_out;

    const int B = in_sizes[1];                 // 8192
    const int D = in_sizes[0] / B;             // 512
    const int C = in_sizes[2] / D;             // 10000

    int nblocks = (B + WARPS_PER_BLOCK - 1) / WARPS_PER_BLOCK;   // 1024
    if (nblocks > MAX_BLOCKS) nblocks = MAX_BLOCKS;

    center_dist_kernel<<<nblocks, WARPS_PER_BLOCK * 32>>>(x, labels, centers, B, D, C);
    finalize_kernel<<<1, 1024>>>(out, nblocks, 1.0f / (float)B);
}